// round 5
// baseline (speedup 1.0000x reference)
#include <cuda_runtime.h>
#include <cuda_fp16.h>
#include <cstdint>

#define NB 8
#define NC 64
#define NH 256
#define NW 512
#define NK 9
#define BHW (NB * NH * NW)          // 1,048,576
#define W4 (NW / 4)                 // 128

typedef unsigned long long ull;

// Scratch: P[k][b][y][x] = sum_c W[c,k] * F[b,c,y,x]   (fp16: 18.9 MB)
__device__ __half g_P[(size_t)NK * BHW];

// Packed f32x2 FMA (sm_100+): d = a*b + c on two lanes at once.
#define FMA_F32X2(d, a, b, c) \
    asm("fma.rn.f32x2 %0, %1, %2, %3;" : "=l"(d) : "l"(a), "l"(b), "l"(c))

// ---------------------------------------------------------------------------
// Pass 1: channel reduction. Each thread owns 4 consecutive x for one (b,y).
// Rolling 8-deep load buffer: consume slot j, immediately refill it from
// channel c+8 -> in-flight pinned at ~8 loads/warp (no drain sawtooth).
// ---------------------------------------------------------------------------
__global__ void __launch_bounds__(256, 3) pass1_kernel(
    const float* __restrict__ feature,   // [B, C, H, W]
    const float* __restrict__ weight)    // [1, C, 3, 3] -> [C, 9]
{
    // Duplicated weights in shared: wdup[c*9+k] = (w, w) for direct f32x2 use.
    __shared__ float2 wdup[NC * NK];
    for (int i = threadIdx.x; i < NC * NK; i += 256) {
        float wv = weight[i];
        wdup[i] = make_float2(wv, wv);
    }
    __syncthreads();

    int g = blockIdx.x * 256 + threadIdx.x;      // [0, B*H*W/4)
    int x4u = g % W4;                             // x/4
    int yb  = g / W4;                             // b*H + y

    const float* fbase = feature
        + ((size_t)(yb / NH) * NC * NH + (yb % NH)) * NW + (size_t)x4u * 4;

    ull acc_lo[NK], acc_hi[NK];
#pragma unroll
    for (int k = 0; k < NK; ++k) { acc_lo[k] = 0ull; acc_hi[k] = 0ull; }

    ull f[8][2];
    // Preload group 0 (channels 0..7), streaming (evict-first; no reuse)
#pragma unroll
    for (int j = 0; j < 8; ++j) {
        const float* p = fbase + (size_t)j * (NH * NW);
        asm volatile("ld.global.cs.v2.u64 {%0, %1}, [%2];"
                     : "=l"(f[j][0]), "=l"(f[j][1]) : "l"(p));
    }

    // Main: consume channel c0+j from slot j, refill slot with channel c0+8+j.
#pragma unroll 1
    for (int c0 = 0; c0 < NC - 8; c0 += 8) {
#pragma unroll
        for (int j = 0; j < 8; ++j) {
            const ull* wp = (const ull*)(wdup + (c0 + j) * NK);
            ull v0 = f[j][0], v1 = f[j][1];
            const float* p = fbase + (size_t)(c0 + 8 + j) * (NH * NW);
            asm volatile("ld.global.cs.v2.u64 {%0, %1}, [%2];"
                         : "=l"(f[j][0]), "=l"(f[j][1]) : "l"(p));
#pragma unroll
            for (int k = 0; k < NK; ++k) {
                ull w = wp[k];
                FMA_F32X2(acc_lo[k], v0, w, acc_lo[k]);
                FMA_F32X2(acc_hi[k], v1, w, acc_hi[k]);
            }
        }
    }
    // Final group (channels 56..63)
#pragma unroll
    for (int j = 0; j < 8; ++j) {
        const ull* wp = (const ull*)(wdup + (NC - 8 + j) * NK);
#pragma unroll
        for (int k = 0; k < NK; ++k) {
            ull w = wp[k];
            FMA_F32X2(acc_lo[k], f[j][0], w, acc_lo[k]);
            FMA_F32X2(acc_hi[k], f[j][1], w, acc_hi[k]);
        }
    }

    // Store: P[k][yb][x4*4 .. +3] as one 8B fp16x4 store per tap
    size_t pbase = (size_t)yb * NW + (size_t)x4u * 4;
#pragma unroll
    for (int k = 0; k < NK; ++k) {
        float2 lo = *(float2*)&acc_lo[k];
        float2 hi = *(float2*)&acc_hi[k];
        __half2 h0 = __floats2half2_rn(lo.x, lo.y);
        __half2 h1 = __floats2half2_rn(hi.x, hi.y);
        uint2 pk;
        pk.x = *(unsigned*)&h0;
        pk.y = *(unsigned*)&h1;
        *(uint2*)(g_P + (size_t)k * BHW + pbase) = pk;
    }
}

// ---------------------------------------------------------------------------
// Pass 2: tap gather + 2x2 upsample. One thread per (h,w) x 4 batches;
// grid.y=2 covers the 8 batches. Indices loaded once, reused across 4 batches.
// ---------------------------------------------------------------------------
__global__ void __launch_bounds__(256) pass2_kernel(
    const int* __restrict__ gi,    // [H, W, 9]
    const int* __restrict__ gj,    // [H, W, 9]
    float* __restrict__ out)       // [B, 1, 2H, 2W]
{
    int g = blockIdx.x * 256 + threadIdx.x;      // [0, H*W)
    int h = g / NW;
    int w = g % NW;
    int ib = g * NK;
    int b0 = blockIdx.y * 4;                      // batch group: 0 or 4

    int ys[NK], xs[NK];
#pragma unroll
    for (int k = 0; k < NK; ++k) ys[k] = gi[ib + k];
#pragma unroll
    for (int k = 0; k < NK; ++k) xs[k] = gj[ib + k];

    float acc[4] = {0.f, 0.f, 0.f, 0.f};
#pragma unroll
    for (int k = 0; k < NK; ++k) {
        const __half* Pk = g_P + (size_t)k * BHW
                         + ((size_t)b0 * NH + ys[k]) * NW + xs[k];
#pragma unroll
        for (int j = 0; j < 4; ++j)
            acc[j] += __half2float(Pk[(size_t)j * NH * NW]);
    }

    // out viewed as float2: [B][2H][NW] (row of 2W floats = NW float2)
    float2* o2 = (float2*)out;
#pragma unroll
    for (int j = 0; j < 4; ++j) {
        float2 v = make_float2(acc[j], acc[j]);
        size_t row0 = ((size_t)(b0 + j) * (2 * NH) + 2 * h) * NW + w;
        o2[row0] = v;
        o2[row0 + NW] = v;
    }
}

// ---------------------------------------------------------------------------
// Launch: graph-capturable, allocation-free.
// Inputs (metadata order): feature f32, weight f32, gi i32, gj i32.
// ---------------------------------------------------------------------------
extern "C" void kernel_launch(void* const* d_in, const int* in_sizes, int n_in,
                              void* d_out, int out_size)
{
    const float* feature = (const float*)d_in[0];
    const float* weight  = (const float*)d_in[1];
    const int*   gi      = (const int*)d_in[2];
    const int*   gj      = (const int*)d_in[3];
    float*       out     = (float*)d_out;

    // Pass 1: B*H*W/4 threads = 262144 -> 1024 blocks of 256
    pass1_kernel<<<BHW / 4 / 256, 256>>>(feature, weight);
    // Pass 2: thread per (h,w) x 4 batches; grid (512, 2) x 256
    dim3 g2(NH * NW / 256, 2);
    pass2_kernel<<<g2, 256>>>(gi, gj, out);
}

// round 7
// speedup vs baseline: 3.3855x; 3.3855x over previous
#include <cuda_runtime.h>
#include <cuda_fp16.h>
#include <cstdint>

#define NB 8
#define NC 64
#define NH 256
#define NW 512
#define NK 9
#define BHW (NB * NH * NW)          // 1,048,576
#define W4 (NW / 4)                 // 128

typedef unsigned long long ull;

// Scratch: P[k][b][y][x] = sum_c W[c,k] * F[b,c,y,x]   (fp16: 18.9 MB, L2-resident)
__device__ __half g_P[(size_t)NK * BHW];

// Packed f32x2 FMA (sm_100+): d = a*b + c on two lanes at once.
#define FMA_F32X2(d, a, b, c) \
    asm("fma.rn.f32x2 %0, %1, %2, %3;" : "=l"(d) : "l"(a), "l"(b), "l"(c))

// ---------------------------------------------------------------------------
// Pass 1: channel reduction. Each thread owns 4 consecutive x for one (b,y).
// Channels in blocks of 8: 8 BACK-TO-BACK streaming 16B loads (MLP 8, no
// interleaving -> no scoreboard-slot sharing pathology), then consume in
// load order. 24 warps/SM x 8 x 128B ~ 24.5KB in flight.
// ---------------------------------------------------------------------------
__global__ void __launch_bounds__(256, 3) pass1_kernel(
    const float* __restrict__ feature,   // [B, C, H, W]
    const float* __restrict__ weight)    // [1, C, 3, 3] -> [C, 9]
{
    // Duplicated weights in shared: wdup[c*9+k] = (w, w) for direct f32x2 use.
    __shared__ float2 wdup[NC * NK];
    for (int i = threadIdx.x; i < NC * NK; i += 256) {
        float wv = weight[i];
        wdup[i] = make_float2(wv, wv);
    }
    __syncthreads();

    int g = blockIdx.x * 256 + threadIdx.x;      // [0, B*H*W/4)
    int x4u = g % W4;                             // x/4
    int yb  = g / W4;                             // b*H + y

    const float* fbase = feature
        + ((size_t)(yb / NH) * NC * NH + (yb % NH)) * NW + (size_t)x4u * 4;

    ull acc_lo[NK], acc_hi[NK];
#pragma unroll
    for (int k = 0; k < NK; ++k) { acc_lo[k] = 0ull; acc_hi[k] = 0ull; }

    for (int c0 = 0; c0 < NC; c0 += 8) {
        ull f[8][2];
        // 8 back-to-back streaming 16B loads (evict-first; no reuse in pass 1)
#pragma unroll
        for (int j = 0; j < 8; ++j) {
            const float* p = fbase + (size_t)(c0 + j) * (NH * NW);
            asm volatile("ld.global.cs.v2.u64 {%0, %1}, [%2];"
                         : "=l"(f[j][0]), "=l"(f[j][1]) : "l"(p));
        }
        // Consume in load order: scoreboard waits only on the oldest load.
#pragma unroll
        for (int j = 0; j < 8; ++j) {
            const ull* wp = (const ull*)(wdup + (c0 + j) * NK);
#pragma unroll
            for (int k = 0; k < NK; ++k) {
                ull w = wp[k];
                FMA_F32X2(acc_lo[k], f[j][0], w, acc_lo[k]);
                FMA_F32X2(acc_hi[k], f[j][1], w, acc_hi[k]);
            }
        }
    }

    // Store: P[k][yb][x4*4 .. +3] as one 8B fp16x4 store per tap.
    // Plain stores (not .cs): P fits in L2 and pass2 rereads it.
    size_t pbase = (size_t)yb * NW + (size_t)x4u * 4;
#pragma unroll
    for (int k = 0; k < NK; ++k) {
        float2 lo = *(float2*)&acc_lo[k];
        float2 hi = *(float2*)&acc_hi[k];
        __half2 h0 = __floats2half2_rn(lo.x, lo.y);
        __half2 h1 = __floats2half2_rn(hi.x, hi.y);
        uint2 pk;
        pk.x = *(unsigned*)&h0;
        pk.y = *(unsigned*)&h1;
        *(uint2*)(g_P + (size_t)k * BHW + pbase) = pk;
    }
}

// ---------------------------------------------------------------------------
// Pass 2: tap gather + 2x2 upsample. One thread per (h,w) x 4 batches;
// grid.y=2 covers the 8 batches. Indices loaded once, reused across 4 batches.
// P is fp16 and L2-resident -> gathers are mostly L2 hits.
// ---------------------------------------------------------------------------
__global__ void __launch_bounds__(256) pass2_kernel(
    const int* __restrict__ gi,    // [H, W, 9]
    const int* __restrict__ gj,    // [H, W, 9]
    float* __restrict__ out)       // [B, 1, 2H, 2W]
{
    int g = blockIdx.x * 256 + threadIdx.x;      // [0, H*W)
    int h = g / NW;
    int w = g % NW;
    int ib = g * NK;
    int b0 = blockIdx.y * 4;                      // batch group: 0 or 4

    int ys[NK], xs[NK];
#pragma unroll
    for (int k = 0; k < NK; ++k) ys[k] = gi[ib + k];
#pragma unroll
    for (int k = 0; k < NK; ++k) xs[k] = gj[ib + k];

    float acc[4] = {0.f, 0.f, 0.f, 0.f};
#pragma unroll
    for (int k = 0; k < NK; ++k) {
        const __half* Pk = g_P + (size_t)k * BHW
                         + ((size_t)b0 * NH + ys[k]) * NW + xs[k];
#pragma unroll
        for (int j = 0; j < 4; ++j)
            acc[j] += __half2float(Pk[(size_t)j * NH * NW]);
    }

    // out viewed as float2: [B][2H][NW] (row of 2W floats = NW float2)
    float2* o2 = (float2*)out;
#pragma unroll
    for (int j = 0; j < 4; ++j) {
        float2 v = make_float2(acc[j], acc[j]);
        size_t row0 = ((size_t)(b0 + j) * (2 * NH) + 2 * h) * NW + w;
        o2[row0] = v;
        o2[row0 + NW] = v;
    }
}

// ---------------------------------------------------------------------------
// Launch: graph-capturable, allocation-free.
// Inputs (metadata order): feature f32, weight f32, gi i32, gj i32.
// ---------------------------------------------------------------------------
extern "C" void kernel_launch(void* const* d_in, const int* in_sizes, int n_in,
                              void* d_out, int out_size)
{
    const float* feature = (const float*)d_in[0];
    const float* weight  = (const float*)d_in[1];
    const int*   gi      = (const int*)d_in[2];
    const int*   gj      = (const int*)d_in[3];
    float*       out     = (float*)d_out;

    // Pass 1: B*H*W/4 threads = 262144 -> 1024 blocks of 256
    pass1_kernel<<<BHW / 4 / 256, 256>>>(feature, weight);
    // Pass 2: thread per (h,w) x 4 batches; grid (512, 2) x 256
    dim3 g2(NH * NW / 256, 2);
    pass2_kernel<<<g2, 256>>>(gi, gj, out);
}

// round 8
// speedup vs baseline: 3.6332x; 1.0732x over previous
#include <cuda_runtime.h>
#include <cuda_fp16.h>
#include <cstdint>

#define NB 8
#define NC 64
#define NH 256
#define NW 512
#define NK 9
#define BHW (NB * NH * NW)          // 1,048,576

typedef unsigned long long ull;

// Scratch: P[k][b][y][x] = sum_c W[c,k] * F[b,c,y,x]   (fp16: 18.9 MB, L2-resident)
__device__ __half g_P[(size_t)NK * BHW];

// Packed f32x2 FMA (sm_100+): d = a*b + c on two lanes at once.
#define FMA_F32X2(d, a, b, c) \
    asm("fma.rn.f32x2 %0, %1, %2, %3;" : "=l"(d) : "l"(a), "l"(b), "l"(c))

__device__ __forceinline__ void cp16(uint32_t dst, const void* src) {
    asm volatile("cp.async.cg.shared.global [%0], [%1], 16;" :: "r"(dst), "l"(src));
}
__device__ __forceinline__ void cpcommit() {
    asm volatile("cp.async.commit_group;");
}
template <int N> __device__ __forceinline__ void cpwait() {
    asm volatile("cp.async.wait_group %0;" :: "n"(N));
}

// ---------------------------------------------------------------------------
// Pass 1: channel reduction, cp.async-pipelined.
// One block per (b,y) row. 64 channels in 8 chunks of 8; 4-stage smem ring
// (16 KB/stage). cp.async decouples in-flight DRAM bytes from registers:
// ~3 blocks/SM x 3 outstanding stages x 16KB ~ 144 KB/SM in flight.
// Each thread owns 2 consecutive x; per chunk: 8 LDS.64 feature +
// 36 broadcast LDS.128 paired weights + 72 FFMA2.
// ---------------------------------------------------------------------------
__global__ void __launch_bounds__(256) pass1_kernel(
    const float* __restrict__ feature,   // [B, C, H, W]
    const float* __restrict__ weight)    // [1, C, 3, 3] -> [C, 9]
{
    extern __shared__ float buf[];       // [4 stages][8 ch][512 x] = 65536 B
    __shared__ float4 sw4[NK][NC / 2];   // {w_c,w_c,w_c1,w_c1} per (k, pair)

    const int t = threadIdx.x;

    for (int i = t; i < NK * (NC / 2); i += 256) {
        int k  = i % NK;
        int cc = i / NK;
        float w0 = weight[(2 * cc + 0) * NK + k];
        float w1 = weight[(2 * cc + 1) * NK + k];
        sw4[k][cc] = make_float4(w0, w0, w1, w1);
    }

    const int yb = blockIdx.x;           // b*NH + y
    const float* frow = feature
        + (size_t)(yb / NH) * NC * NH * NW + (size_t)(yb % NH) * NW;

    const uint32_t sbase = (uint32_t)__cvta_generic_to_shared(buf);

    // Fill stage s with chunk (8 channels): 1024 x 16B, 4 copies per thread.
#define FILL(s, chunk)                                                        \
    do {                                                                      \
        const float* src0 = frow + (size_t)((chunk) * 8) * (NH * NW);         \
        _Pragma("unroll")                                                     \
        for (int i = 0; i < 4; ++i) {                                         \
            int idx = t + i * 256;       /* 0..1023 */                        \
            int cc  = idx >> 7;          /* channel within chunk */           \
            int q   = idx & 127;         /* 16B unit within row */            \
            cp16(sbase + (uint32_t)((s) * 16384 + cc * 2048 + q * 16),        \
                 src0 + (size_t)cc * (NH * NW) + q * 4);                      \
        }                                                                     \
        cpcommit();                                                           \
    } while (0)

    ull acc[NK];
#pragma unroll
    for (int k = 0; k < NK; ++k) acc[k] = 0ull;

    // Prologue: 3 stages in flight.
    FILL(0, 0);
    FILL(1, 1);
    FILL(2, 2);
    __syncthreads();                     // also publishes sw4

#pragma unroll
    for (int chunk = 0; chunk < 8; ++chunk) {
        // Allow pending = min(2, 7 - chunk) so chunk's stage is complete.
        if (chunk < 6)       cpwait<2>();
        else if (chunk == 6) cpwait<1>();
        else                 cpwait<0>();
        __syncthreads();                 // cross-thread visibility of stage

        const float* st = buf + (chunk & 3) * 4096;
#pragma unroll
        for (int p = 0; p < 4; ++p) {    // channel pairs within chunk
            ull f0 = *(const ull*)(st + (2 * p + 0) * 512 + 2 * t);
            ull f1 = *(const ull*)(st + (2 * p + 1) * 512 + 2 * t);
            int cidx = chunk * 4 + p;    // global pair index 0..31
#pragma unroll
            for (int k = 0; k < NK; ++k) {
                ulonglong2 wp = *(const ulonglong2*)&sw4[k][cidx];
                FMA_F32X2(acc[k], f0, wp.x, acc[k]);
                FMA_F32X2(acc[k], f1, wp.y, acc[k]);
            }
        }
        __syncthreads();                 // all consumers done before refill
        if (chunk + 3 < 8) FILL((chunk + 3) & 3, chunk + 3);
    }
#undef FILL

    // Store: thread owns x = {2t, 2t+1}; one 4B half2 store per tap.
    size_t pbase = (size_t)yb * NW + 2 * t;
#pragma unroll
    for (int k = 0; k < NK; ++k) {
        float2 v = *(float2*)&acc[k];
        __half2 h = __floats2half2_rn(v.x, v.y);
        *(__half2*)(g_P + (size_t)k * BHW + pbase) = h;
    }
}

// ---------------------------------------------------------------------------
// Pass 2: tap gather + 2x2 upsample. One thread per (h,w) x 4 batches;
// grid.y=2 covers the 8 batches. Indices loaded once, reused across 4 batches.
// P is fp16 and L2-resident -> gathers are mostly L2 hits.
// ---------------------------------------------------------------------------
__global__ void __launch_bounds__(256) pass2_kernel(
    const int* __restrict__ gi,    // [H, W, 9]
    const int* __restrict__ gj,    // [H, W, 9]
    float* __restrict__ out)       // [B, 1, 2H, 2W]
{
    int g = blockIdx.x * 256 + threadIdx.x;      // [0, H*W)
    int h = g / NW;
    int w = g % NW;
    int ib = g * NK;
    int b0 = blockIdx.y * 4;                      // batch group: 0 or 4

    int ys[NK], xs[NK];
#pragma unroll
    for (int k = 0; k < NK; ++k) ys[k] = gi[ib + k];
#pragma unroll
    for (int k = 0; k < NK; ++k) xs[k] = gj[ib + k];

    float acc[4] = {0.f, 0.f, 0.f, 0.f};
#pragma unroll
    for (int k = 0; k < NK; ++k) {
        const __half* Pk = g_P + (size_t)k * BHW
                         + ((size_t)b0 * NH + ys[k]) * NW + xs[k];
#pragma unroll
        for (int j = 0; j < 4; ++j)
            acc[j] += __half2float(Pk[(size_t)j * NH * NW]);
    }

    // out viewed as float2: [B][2H][NW] (row of 2W floats = NW float2)
    float2* o2 = (float2*)out;
#pragma unroll
    for (int j = 0; j < 4; ++j) {
        float2 v = make_float2(acc[j], acc[j]);
        size_t row0 = ((size_t)(b0 + j) * (2 * NH) + 2 * h) * NW + w;
        o2[row0] = v;
        o2[row0 + NW] = v;
    }
}

// ---------------------------------------------------------------------------
// Launch: graph-capturable, allocation-free.
// Inputs (metadata order): feature f32, weight f32, gi i32, gj i32.
// ---------------------------------------------------------------------------
extern "C" void kernel_launch(void* const* d_in, const int* in_sizes, int n_in,
                              void* d_out, int out_size)
{
    const float* feature = (const float*)d_in[0];
    const float* weight  = (const float*)d_in[1];
    const int*   gi      = (const int*)d_in[2];
    const int*   gj      = (const int*)d_in[3];
    float*       out     = (float*)d_out;

    // 64 KB dynamic smem needs an explicit opt-in (idempotent host call).
    static bool attr_set = false;
    if (!attr_set) {
        cudaFuncSetAttribute(pass1_kernel,
                             cudaFuncAttributeMaxDynamicSharedMemorySize, 65536);
        attr_set = true;
    }

    // Pass 1: one block per (b,y) row: 2048 blocks x 256 threads, 64KB smem
    pass1_kernel<<<NB * NH, 256, 65536>>>(feature, weight);
    // Pass 2: thread per (h,w) x 4 batches; grid (512, 2) x 256
    dim3 g2(NH * NW / 256, 2);
    pass2_kernel<<<g2, 256>>>(gi, gj, out);
}